// round 2
// baseline (speedup 1.0000x reference)
#include <cuda_runtime.h>
#include <math.h>

#define BB 2
#define SS_ 2048
#define DD 512
#define HH 8
#define DKV 64
#define DFF 2048
#define NTOK (BB*SS_)          // 4096
#define EPS 1e-5f

// ------------------------------ scratch (device globals; no allocation) ----
__device__ float g_qb[BB*HH*SS_*DKV];      // [B,H,S,64]
__device__ float g_kb[BB*HH*SS_*DKV];
__device__ float g_vb[BB*HH*SS_*DKV];
__device__ float g_ctx[NTOK*DD];           // [N,512] token-major context
__device__ float g_t1[NTOK*DD];            // pre-LN1
__device__ float g_ao[NTOK*DD];            // attn_out (post LN1)
__device__ float g_h[NTOK*DFF];            // relu hidden
__device__ float g_t2[NTOK*DD];            // pre-LN2
__device__ int   g_maskmode;               // 0 = int32 mask, 1 = uint8 mask

// ------------------------------ mask dtype detection -----------------------
// If the bool mask is materialized as int32, every 32-bit word is exactly 0 or
// 1. If it is byte-packed bools, words are packed combos (e.g. 0x00010101) and
// with ~50% ones the chance that 4096 consecutive words are all <=1 is ~0.
__global__ void detect_mask_kernel(const unsigned int* __restrict__ m)
{
    if (threadIdx.x == 0 && blockIdx.x == 0) {
        int mode = 0;
        for (int i = 0; i < 4096; i++) {
            if (m[i] > 1u) { mode = 1; break; }
        }
        g_maskmode = mode;
    }
}

// ------------------------------ generic fp32 GEMM: C = A[M,K] @ W[K,N] -----
// 128x128 CTA tile, 8x8 per thread, BK=8. Optional bias/residual/relu.
// headStore: write into [B,H,S,64] layout (for Q/K/V).
__global__ __launch_bounds__(256) void sgemm_kernel(
    const float* __restrict__ A, const float* __restrict__ W,
    const float* __restrict__ bias, const float* __restrict__ resid,
    float* __restrict__ C, int M, int N, int K, int doRelu, int headStore)
{
    __shared__ float As[8][132];
    __shared__ float Bs[8][128];
    int tid = threadIdx.x;
    int rowBase = blockIdx.y * 128;
    int colBase = blockIdx.x * 128;
    int ty = tid >> 4, tx = tid & 15;

    int a_m = tid >> 1;            // 0..127
    int a_k4 = (tid & 1) * 4;      // 0 or 4
    int b_k = tid >> 5;            // 0..7
    int b_n4 = (tid & 31) * 4;     // 0..124

    const float* Ap = A + (size_t)(rowBase + a_m) * K + a_k4;
    const float* Wp = W + colBase + b_n4;

    float acc[8][8];
#pragma unroll
    for (int i = 0; i < 8; i++)
#pragma unroll
        for (int j = 0; j < 8; j++) acc[i][j] = 0.f;

    for (int k0 = 0; k0 < K; k0 += 8) {
        float4 av = *(const float4*)(Ap + k0);
        float4 bv = *(const float4*)(Wp + (size_t)(k0 + b_k) * N);
        __syncthreads();
        As[a_k4 + 0][a_m] = av.x;
        As[a_k4 + 1][a_m] = av.y;
        As[a_k4 + 2][a_m] = av.z;
        As[a_k4 + 3][a_m] = av.w;
        *(float4*)&Bs[b_k][b_n4] = bv;
        __syncthreads();
#pragma unroll
        for (int kk = 0; kk < 8; kk++) {
            float4 a0 = *(float4*)&As[kk][ty * 8];
            float4 a1 = *(float4*)&As[kk][ty * 8 + 4];
            float4 b0 = *(float4*)&Bs[kk][tx * 8];
            float4 b1 = *(float4*)&Bs[kk][tx * 8 + 4];
            float ra[8] = {a0.x, a0.y, a0.z, a0.w, a1.x, a1.y, a1.z, a1.w};
            float rb[8] = {b0.x, b0.y, b0.z, b0.w, b1.x, b1.y, b1.z, b1.w};
#pragma unroll
            for (int i = 0; i < 8; i++)
#pragma unroll
                for (int j = 0; j < 8; j++) acc[i][j] = fmaf(ra[i], rb[j], acc[i][j]);
        }
    }

#pragma unroll
    for (int i = 0; i < 8; i++) {
        int row = rowBase + ty * 8 + i;
#pragma unroll
        for (int j = 0; j < 8; j++) {
            int col = colBase + tx * 8 + j;
            float c = acc[i][j] + bias[col];
            if (resid) c += resid[(size_t)row * N + col];
            if (doRelu) c = fmaxf(c, 0.f);
            if (headStore) {
                int b_ = row / SS_, s_ = row % SS_;
                int h_ = col >> 6, d_ = col & 63;
                C[(((size_t)(b_ * HH + h_)) * SS_ + s_) * 64 + d_] = c;
            } else {
                C[(size_t)row * N + col] = c;
            }
        }
    }
}

// ------------------------------ fused attention ---------------------------
// grid (S/16, B*H), 256 threads. Per CTA: 16 query rows, full 2048 keys.
// SMEM strip holds masked/scaled scores -> softmax in place -> attn written
// to gmem once -> attn @ V computed from SMEM (no gmem re-read).
#define SSP 2052                    // padded row stride (bank-shift, 16B align)
#define ATTN_SMEM_FLOATS (16*SSP + 16384 + 1024 + 16)
#define ATTN_SMEM_BYTES  (ATTN_SMEM_FLOATS * 4)

__global__ __launch_bounds__(256) void attn_kernel(
    const float* __restrict__ q, const float* __restrict__ k,
    const float* __restrict__ v, const void* __restrict__ mask,
    float* __restrict__ attn, float* __restrict__ ctx)
{
    extern __shared__ float smem[];
    float* ss  = smem;                 // 16 x SSP  (scores / exp values)
    float* kvs = smem + 16 * SSP;      // 16384 floats: k^T [64][132] or v [2][128][64]
    float* pbuf = kvs + 16384;         // 1024 floats: q stage / partial combine
    float* invs = pbuf + 1024;         // 16 floats: per-row 1/sum

    int tid = threadIdx.x;
    int bh = blockIdx.y;               // b*H + h
    int b_ = bh >> 3;                  // H=8
    int h_ = bh & 7;
    int row0 = blockIdx.x * 16;
    int maskmode = g_maskmode;

    const float* qptr = q + ((size_t)bh * SS_ + row0) * 64;
    const float* kptr = k + (size_t)bh * SS_ * 64;
    const float* vptr = v + (size_t)bh * SS_ * 64;
    const int* maskp32 = (const int*)mask + (size_t)b_ * SS_ * SS_;
    const unsigned char* maskp8 = (const unsigned char*)mask + (size_t)b_ * SS_ * SS_;

    // load 16x64 q tile (contiguous) into pbuf (untouched until final combine)
    ((float4*)pbuf)[tid] = ((const float4*)qptr)[tid];
    __syncthreads();
    float* qs = pbuf;

    int wy = tid >> 5;                 // warp id = row pair (wy, wy+8)
    int lx = tid & 31;                 // lane -> 4 consecutive cols

    // ---------------- scores: 16 tiles of 128 keys ----------------
    for (int ct = 0; ct < 16; ct++) {
        __syncthreads();
        // load k tile transposed into kvs[d][col], padded stride 132
#pragma unroll
        for (int t = 0; t < 8; t++) {
            int idx = tid + t * 256;
            int col = idx >> 4;
            int d4 = (idx & 15) << 2;
            float4 kv4 = *(const float4*)(kptr + (size_t)(ct * 128 + col) * 64 + d4);
            kvs[(d4 + 0) * 132 + col] = kv4.x;
            kvs[(d4 + 1) * 132 + col] = kv4.y;
            kvs[(d4 + 2) * 132 + col] = kv4.z;
            kvs[(d4 + 3) * 132 + col] = kv4.w;
        }
        __syncthreads();

        float a0[4] = {0.f, 0.f, 0.f, 0.f};
        float a1[4] = {0.f, 0.f, 0.f, 0.f};
#pragma unroll 8
        for (int d = 0; d < 64; d++) {
            float q0 = qs[wy * 64 + d];
            float q1 = qs[(wy + 8) * 64 + d];
            float4 k4 = *(float4*)&kvs[d * 132 + lx * 4];
            a0[0] = fmaf(q0, k4.x, a0[0]); a0[1] = fmaf(q0, k4.y, a0[1]);
            a0[2] = fmaf(q0, k4.z, a0[2]); a0[3] = fmaf(q0, k4.w, a0[3]);
            a1[0] = fmaf(q1, k4.x, a1[0]); a1[1] = fmaf(q1, k4.y, a1[1]);
            a1[2] = fmaf(q1, k4.z, a1[2]); a1[3] = fmaf(q1, k4.w, a1[3]);
        }
        int c0 = ct * 128 + lx * 4;
        int m0x, m0y, m0z, m0w, m1x, m1y, m1z, m1w;
        if (maskmode == 0) {
            int4 mi0 = *(const int4*)(maskp32 + (size_t)(row0 + wy) * SS_ + c0);
            int4 mi1 = *(const int4*)(maskp32 + (size_t)(row0 + wy + 8) * SS_ + c0);
            m0x = mi0.x; m0y = mi0.y; m0z = mi0.z; m0w = mi0.w;
            m1x = mi1.x; m1y = mi1.y; m1z = mi1.z; m1w = mi1.w;
        } else {
            uchar4 mb0 = *(const uchar4*)(maskp8 + (size_t)(row0 + wy) * SS_ + c0);
            uchar4 mb1 = *(const uchar4*)(maskp8 + (size_t)(row0 + wy + 8) * SS_ + c0);
            m0x = mb0.x; m0y = mb0.y; m0z = mb0.z; m0w = mb0.w;
            m1x = mb1.x; m1y = mb1.y; m1z = mb1.z; m1w = mb1.w;
        }
        float4 s0v, s1v;
        s0v.x = m0x ? -1e9f : a0[0] * 0.125f;
        s0v.y = m0y ? -1e9f : a0[1] * 0.125f;
        s0v.z = m0z ? -1e9f : a0[2] * 0.125f;
        s0v.w = m0w ? -1e9f : a0[3] * 0.125f;
        s1v.x = m1x ? -1e9f : a1[0] * 0.125f;
        s1v.y = m1y ? -1e9f : a1[1] * 0.125f;
        s1v.z = m1z ? -1e9f : a1[2] * 0.125f;
        s1v.w = m1w ? -1e9f : a1[3] * 0.125f;
        *(float4*)&ss[wy * SSP + c0] = s0v;
        *(float4*)&ss[(wy + 8) * SSP + c0] = s1v;
    }

    // ---------------- softmax (each warp owns rows wy, wy+8) ----------------
    float mx0 = -1e30f, mx1 = -1e30f;
#pragma unroll
    for (int ct = 0; ct < 16; ct++) {
        int c0 = ct * 128 + lx * 4;
        float4 x0 = *(float4*)&ss[wy * SSP + c0];
        float4 x1 = *(float4*)&ss[(wy + 8) * SSP + c0];
        mx0 = fmaxf(mx0, fmaxf(fmaxf(x0.x, x0.y), fmaxf(x0.z, x0.w)));
        mx1 = fmaxf(mx1, fmaxf(fmaxf(x1.x, x1.y), fmaxf(x1.z, x1.w)));
    }
#pragma unroll
    for (int o = 16; o; o >>= 1) {
        mx0 = fmaxf(mx0, __shfl_xor_sync(0xffffffffu, mx0, o));
        mx1 = fmaxf(mx1, __shfl_xor_sync(0xffffffffu, mx1, o));
    }
    float sm0 = 0.f, sm1 = 0.f;
#pragma unroll
    for (int ct = 0; ct < 16; ct++) {
        int c0 = ct * 128 + lx * 4;
        float4 x0 = *(float4*)&ss[wy * SSP + c0];
        float4 x1 = *(float4*)&ss[(wy + 8) * SSP + c0];
        x0.x = __expf(x0.x - mx0); x0.y = __expf(x0.y - mx0);
        x0.z = __expf(x0.z - mx0); x0.w = __expf(x0.w - mx0);
        x1.x = __expf(x1.x - mx1); x1.y = __expf(x1.y - mx1);
        x1.z = __expf(x1.z - mx1); x1.w = __expf(x1.w - mx1);
        sm0 += x0.x + x0.y + x0.z + x0.w;
        sm1 += x1.x + x1.y + x1.z + x1.w;
        *(float4*)&ss[wy * SSP + c0] = x0;        // keep e (unnormalized)
        *(float4*)&ss[(wy + 8) * SSP + c0] = x1;
    }
#pragma unroll
    for (int o = 16; o; o >>= 1) {
        sm0 += __shfl_xor_sync(0xffffffffu, sm0, o);
        sm1 += __shfl_xor_sync(0xffffffffu, sm1, o);
    }
    float inv0 = 1.f / sm0, inv1 = 1.f / sm1;
    if (lx == 0) { invs[wy] = inv0; invs[wy + 8] = inv1; }

    if (attn) {   // required output: write normalized probs once
#pragma unroll
        for (int ct = 0; ct < 16; ct++) {
            int c0 = ct * 128 + lx * 4;
            float4 x0 = *(float4*)&ss[wy * SSP + c0];
            float4 x1 = *(float4*)&ss[(wy + 8) * SSP + c0];
            x0.x *= inv0; x0.y *= inv0; x0.z *= inv0; x0.w *= inv0;
            x1.x *= inv1; x1.y *= inv1; x1.z *= inv1; x1.w *= inv1;
            *(float4*)(attn + ((size_t)bh * SS_ + row0 + wy) * SS_ + c0) = x0;
            *(float4*)(attn + ((size_t)bh * SS_ + row0 + wy + 8) * SS_ + c0) = x1;
        }
    }

    // ---------------- attn @ V (kk-split halves), scale by inv at end ------
    int g = tid >> 7;                  // 0: kk 0..1023   1: kk 1024..2047
    int t = tid & 127;
    int tyv = t >> 4;                  // rows tyv, tyv+8
    int cv = (t & 15) << 2;            // 4 consecutive v cols
    float vacc0[4] = {0.f, 0.f, 0.f, 0.f};
    float vacc1[4] = {0.f, 0.f, 0.f, 0.f};

    for (int step = 0; step < 8; step++) {
        __syncthreads();   // prev compute done reading kvs (1st iter: softmax done)
#pragma unroll
        for (int t2 = 0; t2 < 16; t2++) {
            int idx = tid + t2 * 256;            // 0..4095
            int gg = idx >> 11;
            int rem = idx & 2047;
            int kk = rem >> 4;
            int c4 = (rem & 15) << 2;
            int tile = gg ? (step + 8) : step;
            *(float4*)&kvs[gg * 8192 + kk * 64 + c4] =
                *(const float4*)(vptr + (size_t)(tile * 128 + kk) * 64 + c4);
        }
        __syncthreads();
        int colbase = (g ? (step + 8) : step) * 128;
#pragma unroll 8
        for (int kk = 0; kk < 128; kk++) {
            float p0 = ss[tyv * SSP + colbase + kk];
            float p1 = ss[(tyv + 8) * SSP + colbase + kk];
            float4 v4 = *(float4*)&kvs[g * 8192 + kk * 64 + cv];
            vacc0[0] = fmaf(p0, v4.x, vacc0[0]); vacc0[1] = fmaf(p0, v4.y, vacc0[1]);
            vacc0[2] = fmaf(p0, v4.z, vacc0[2]); vacc0[3] = fmaf(p0, v4.w, vacc0[3]);
            vacc1[0] = fmaf(p1, v4.x, vacc1[0]); vacc1[1] = fmaf(p1, v4.y, vacc1[1]);
            vacc1[2] = fmaf(p1, v4.z, vacc1[2]); vacc1[3] = fmaf(p1, v4.w, vacc1[3]);
        }
    }
    __syncthreads();                   // done with q staged in pbuf; reuse it
    if (g == 1) {
        float* p = pbuf + t * 8;
        p[0] = vacc0[0]; p[1] = vacc0[1]; p[2] = vacc0[2]; p[3] = vacc0[3];
        p[4] = vacc1[0]; p[5] = vacc1[1]; p[6] = vacc1[2]; p[7] = vacc1[3];
    }
    __syncthreads();
    if (g == 0) {
        float* p = pbuf + t * 8;
        float i0 = invs[tyv], i1 = invs[tyv + 8];
        float4 o0, o1;
        o0.x = (vacc0[0] + p[0]) * i0; o0.y = (vacc0[1] + p[1]) * i0;
        o0.z = (vacc0[2] + p[2]) * i0; o0.w = (vacc0[3] + p[3]) * i0;
        o1.x = (vacc1[0] + p[4]) * i1; o1.y = (vacc1[1] + p[5]) * i1;
        o1.z = (vacc1[2] + p[6]) * i1; o1.w = (vacc1[3] + p[7]) * i1;
        int gr0 = row0 + tyv, gr1 = row0 + tyv + 8;
        *(float4*)&ctx[((size_t)(b_ * SS_ + gr0)) * DD + h_ * 64 + cv] = o0;
        *(float4*)&ctx[((size_t)(b_ * SS_ + gr1)) * DD + h_ * 64 + cv] = o1;
    }
}

// ------------------------------ layernorm over rows of 512 -----------------
__global__ __launch_bounds__(128) void ln_kernel(
    const float* __restrict__ x, const float* __restrict__ gamma,
    const float* __restrict__ beta, float* __restrict__ out)
{
    int row = blockIdx.x;
    int tid = threadIdx.x;
    __shared__ float red[4];
    float4 v = ((const float4*)(x + (size_t)row * DD))[tid];
    float s = v.x + v.y + v.z + v.w;
#pragma unroll
    for (int o = 16; o; o >>= 1) s += __shfl_xor_sync(0xffffffffu, s, o);
    if ((tid & 31) == 0) red[tid >> 5] = s;
    __syncthreads();
    float mu = (red[0] + red[1] + red[2] + red[3]) * (1.f / DD);
    float dx = v.x - mu, dy = v.y - mu, dz = v.z - mu, dw = v.w - mu;
    float s2 = dx * dx + dy * dy + dz * dz + dw * dw;
#pragma unroll
    for (int o = 16; o; o >>= 1) s2 += __shfl_xor_sync(0xffffffffu, s2, o);
    __syncthreads();
    if ((tid & 31) == 0) red[tid >> 5] = s2;
    __syncthreads();
    float var = (red[0] + red[1] + red[2] + red[3]) * (1.f / DD);
    float inv = rsqrtf(var + EPS);
    float4 gg = ((const float4*)gamma)[tid];
    float4 bb = ((const float4*)beta)[tid];
    float4 o;
    o.x = dx * inv * gg.x + bb.x;
    o.y = dy * inv * gg.y + bb.y;
    o.z = dz * inv * gg.z + bb.z;
    o.w = dw * inv * gg.w + bb.w;
    *(float4*)(out + (size_t)row * DD + tid * 4) = o;
}

// ------------------------------ launch -------------------------------------
extern "C" void kernel_launch(void* const* d_in, const int* in_sizes, int n_in,
                              void* d_out, int out_size)
{
    const float* x   = (const float*)d_in[0];
    const void*  mask = d_in[1];
    const float* Wq  = (const float*)d_in[2];
    const float* bq  = (const float*)d_in[3];
    const float* Wk  = (const float*)d_in[4];
    const float* bk  = (const float*)d_in[5];
    const float* Wv  = (const float*)d_in[6];
    const float* bv  = (const float*)d_in[7];
    const float* Wo  = (const float*)d_in[8];
    const float* bo  = (const float*)d_in[9];
    const float* ln1g = (const float*)d_in[10];
    const float* ln1b = (const float*)d_in[11];
    const float* W1  = (const float*)d_in[12];
    const float* b1  = (const float*)d_in[13];
    const float* W2  = (const float*)d_in[14];
    const float* b2  = (const float*)d_in[15];
    const float* ln2g = (const float*)d_in[16];
    const float* ln2b = (const float*)d_in[17];

    float* out = (float*)d_out;
    const long OUT_ELEMS = (long)BB * SS_ * DD;            // 2,097,152
    const long ATTN_ELEMS = (long)BB * HH * SS_ * SS_;     // 67,108,864
    float* attn_ptr = ((long)out_size >= OUT_ELEMS + ATTN_ELEMS)
                        ? (out + OUT_ELEMS) : nullptr;

    float *qp, *kp, *vp, *ctxp, *t1p, *aop, *hp, *t2p;
    cudaGetSymbolAddress((void**)&qp, g_qb);
    cudaGetSymbolAddress((void**)&kp, g_kb);
    cudaGetSymbolAddress((void**)&vp, g_vb);
    cudaGetSymbolAddress((void**)&ctxp, g_ctx);
    cudaGetSymbolAddress((void**)&t1p, g_t1);
    cudaGetSymbolAddress((void**)&aop, g_ao);
    cudaGetSymbolAddress((void**)&hp, g_h);
    cudaGetSymbolAddress((void**)&t2p, g_t2);

    cudaFuncSetAttribute(attn_kernel,
                         cudaFuncAttributeMaxDynamicSharedMemorySize,
                         ATTN_SMEM_BYTES);

    dim3 blk(256);
    // mask dtype probe (device-side, graph-capturable, deterministic)
    detect_mask_kernel<<<1, 32>>>((const unsigned int*)mask);
    // QKV projections (store into [B,H,S,64])
    sgemm_kernel<<<dim3(4, 32), blk>>>(x, Wq, bq, nullptr, qp, NTOK, DD, DD, 0, 1);
    sgemm_kernel<<<dim3(4, 32), blk>>>(x, Wk, bk, nullptr, kp, NTOK, DD, DD, 0, 1);
    sgemm_kernel<<<dim3(4, 32), blk>>>(x, Wv, bv, nullptr, vp, NTOK, DD, DD, 0, 1);
    // fused attention (scores+mask+softmax+attn-out+context)
    attn_kernel<<<dim3(SS_ / 16, BB * HH), blk, ATTN_SMEM_BYTES>>>(
        qp, kp, vp, mask, attn_ptr, ctxp);
    // Wo projection + residual, then LN1
    sgemm_kernel<<<dim3(4, 32), blk>>>(ctxp, Wo, bo, x, t1p, NTOK, DD, DD, 0, 0);
    ln_kernel<<<NTOK, 128>>>(t1p, ln1g, ln1b, aop);
    // FFN
    sgemm_kernel<<<dim3(16, 32), blk>>>(aop, W1, b1, nullptr, hp, NTOK, DFF, DD, 1, 0);
    sgemm_kernel<<<dim3(4, 32), blk>>>(hp, W2, b2, aop, t2p, NTOK, DD, DFF, 0, 0);
    ln_kernel<<<NTOK, 128>>>(t2p, ln2g, ln2b, out);
}